// round 3
// baseline (speedup 1.0000x reference)
#include <cuda_runtime.h>
#include <cstdint>

#define MODES 16
#define LOG2E 1.4426950408889634f
#define LN2   0.6931471805599453f
#define E_CONST 2.7182818284590452f
#define TAU   0.25f   /* 1/sqrt(16) */

#define VMIN_BLOCKS 296

// Scratch: per-block partial minima (plain stores, needs no init) + ticket.
__device__ float    g_part[VMIN_BLOCKS][MODES];
__device__ float    g_vmin[MODES];
__device__ unsigned g_ticket;   // static-init 0; last block resets to 0 -> replay-safe

__device__ __forceinline__ float ex2_approx(float x) {
    float r;
    asm("ex2.approx.f32 %0, %1;" : "=f"(r) : "f"(x));
    return r;
}
__device__ __forceinline__ float rcp_approx(float x) {
    float r;
    asm("rcp.approx.f32 %0, %1;" : "=f"(r) : "f"(x));
    return r;
}

// Packed f32x2 exp2 for two independent exponents (keeps MUFU free; fp pipe does
// 2 lanes per FFMA2). Valid for e in ~[-100, 100]; here e in ~[1, 4].
__device__ __forceinline__ void exp2_poly2(float e1, float e2, float& r1, float& r2) {
    const unsigned long long MAGIC  = 0x4B4000004B400000ULL;  // (12582912, 12582912)
    const unsigned long long NMAGIC = 0xCB400000CB400000ULL;  // negated
    const unsigned long long NONE   = 0xBF800000BF800000ULL;  // (-1, -1)
    const unsigned long long C5     = 0x3AAEC8D83AAEC8D8ULL;  // 0.00133335581
    const unsigned long long C4     = 0x3C1D962C3C1D962CULL;  // 0.00961812911
    const unsigned long long C3     = 0x3D6357703D635770ULL;  // 0.05550410866
    const unsigned long long C2     = 0x3E75FDF03E75FDF0ULL;  // 0.24022650696
    const unsigned long long C1     = 0x3F3172183F317218ULL;  // 0.69314718056
    const unsigned long long ONE    = 0x3F8000003F800000ULL;  // (1, 1)

    unsigned long long e, y, k, f, p;
    asm("mov.b64 %0, {%1, %2};" : "=l"(e) : "f"(e1), "f"(e2));
    asm("add.rn.f32x2 %0, %1, %2;" : "=l"(y) : "l"(e), "l"(MAGIC));   // mantissa holds round(e)
    asm("add.rn.f32x2 %0, %1, %2;" : "=l"(k) : "l"(y), "l"(NMAGIC));  // (float)round(e)
    asm("fma.rn.f32x2 %0, %1, %2, %3;" : "=l"(f) : "l"(k), "l"(NONE), "l"(e));  // f = e - k
    asm("fma.rn.f32x2 %0, %1, %2, %3;" : "=l"(p) : "l"(f), "l"(C5), "l"(C4));
    asm("fma.rn.f32x2 %0, %1, %2, %3;" : "=l"(p) : "l"(f), "l"(p), "l"(C3));
    asm("fma.rn.f32x2 %0, %1, %2, %3;" : "=l"(p) : "l"(f), "l"(p), "l"(C2));
    asm("fma.rn.f32x2 %0, %1, %2, %3;" : "=l"(p) : "l"(f), "l"(p), "l"(C1));
    asm("fma.rn.f32x2 %0, %1, %2, %3;" : "=l"(p) : "l"(f), "l"(p), "l"(ONE));

    unsigned plo, phi_, ylo, yhi;
    asm("mov.b64 {%0, %1}, %2;" : "=r"(plo), "=r"(phi_) : "l"(p));
    asm("mov.b64 {%0, %1}, %2;" : "=r"(ylo), "=r"(yhi) : "l"(y));
    r1 = __uint_as_float(plo + (ylo << 23));   // low 9 bits of magic are 0 -> exact k<<23
    r2 = __uint_as_float(phi_ + (yhi << 23));
}

// Per-column min over V[N, 16] with last-block final reduce (no init kernel).
__global__ void __launch_bounds__(256) comp_vmin_kernel(const float* __restrict__ V, int N) {
    float m[MODES];
#pragma unroll
    for (int j = 0; j < MODES; j++) m[j] = 3.4028235e38f;

    int stride = gridDim.x * blockDim.x;
    for (int r = blockIdx.x * blockDim.x + threadIdx.x; r < N; r += stride) {
        const float4* p = (const float4*)(V + (size_t)r * MODES);
#pragma unroll
        for (int q = 0; q < 4; q++) {
            float4 v = p[q];
            m[4 * q + 0] = fminf(m[4 * q + 0], v.x);
            m[4 * q + 1] = fminf(m[4 * q + 1], v.y);
            m[4 * q + 2] = fminf(m[4 * q + 2], v.z);
            m[4 * q + 3] = fminf(m[4 * q + 3], v.w);
        }
    }
#pragma unroll
    for (int off = 16; off; off >>= 1) {
#pragma unroll
        for (int j = 0; j < MODES; j++)
            m[j] = fminf(m[j], __shfl_xor_sync(0xFFFFFFFFu, m[j], off));
    }
    __shared__ float sred[8][MODES];
    int warp = threadIdx.x >> 5, lane = threadIdx.x & 31;
    if (lane == 0) {
#pragma unroll
        for (int j = 0; j < MODES; j++) sred[warp][j] = m[j];
    }
    __syncthreads();
    if (threadIdx.x < MODES) {
        float mm = sred[0][threadIdx.x];
#pragma unroll
        for (int wq = 1; wq < 8; wq++) mm = fminf(mm, sred[wq][threadIdx.x]);
        g_part[blockIdx.x][threadIdx.x] = mm;
    }
    // ticket: last block reduces partials and resets the ticket
    __threadfence();
    __shared__ bool is_last;
    __syncthreads();
    if (threadIdx.x == 0)
        is_last = (atomicAdd(&g_ticket, 1u) == gridDim.x - 1);
    __syncthreads();
    if (is_last) {
        if (threadIdx.x < MODES) {
            float mm = 3.4028235e38f;
            for (int bq = 0; bq < VMIN_BLOCKS; bq++)
                mm = fminf(mm, g_part[bq][threadIdx.x]);
            g_vmin[threadIdx.x] = mm;
        }
        if (threadIdx.x == 0) g_ticket = 0;
    }
}

// One row per thread. phi -> pairwise power interpolation -> modal -> log_softmax.
// Pairs with j-i >= 11 go through packed-f32x2 polynomial exp2 (fp pipe);
// the rest use MUFU ex2. Split chosen so T_fp ~= T_mufu.
__global__ void __launch_bounds__(128) comp_main_kernel(
    const float* __restrict__ V,
    const float* __restrict__ w,
    const float* __restrict__ b,
    const float* __restrict__ gammas,
    float* __restrict__ out, int N)
{
    __shared__ float Gs[MODES][MODES];
    __shared__ float sw[MODES], sb[MODES], svmin[MODES];
    int t = threadIdx.x;
    if (t < MODES * MODES) {        // 128 threads -> 2 entries each
#pragma unroll
        for (int rep = 0; rep < 2; rep++) {
            int e = t + rep * 128;
            int i = e >> 4, j = e & 15;
            float g = 0.0f;
            if (j > i)      g = gammas[i * MODES + j];
            else if (j < i) g = gammas[j * MODES + i];
            Gs[i][j] = g;
        }
    }
    if (t < MODES) {
        sw[t] = 1.0f + w[t];
        sb[t] = b[t];
        svmin[t] = g_vmin[t];
    }
    __syncthreads();

    int r = blockIdx.x * blockDim.x + t;
    if (r >= N) return;

    float acc[MODES], L[MODES];
    {
        const float4* p = (const float4*)(V + (size_t)r * MODES);
#pragma unroll
        for (int q = 0; q < 4; q++) {
            float4 v = p[q];
            float vv[4] = {v.x, v.y, v.z, v.w};
#pragma unroll
            for (int k = 0; k < 4; k++) {
                int j = 4 * q + k;
                float vc = fmaxf(vv[k] - svmin[j] + E_CONST, E_CONST);
                float ph = fmaf(sw[j], vc, sb[j]);
                acc[j] = ph;                 // diagonal term seeds the sum
                L[j] = __log2f(ph);
            }
        }
    }

    // acc_i += sum_{j != i} 2^( g*(L_i - L_j) + L_j )
#pragma unroll
    for (int i = 0; i < MODES; i++) {
#pragma unroll
        for (int j = i + 1; j < MODES; j++) {
            float g = Gs[i][j];
            float d = L[i] - L[j];
            float e1 = fmaf(g, d, L[j]);     // exponent of P[i][j]
            float e2 = fmaf(-g, d, L[i]);    // exponent of P[j][i]
            float p1, p2;
            if (j - i >= 11) {               // compile-time: packed poly (fp pipe)
                exp2_poly2(e1, e2, p1, p2);
            } else {                         // MUFU path
                p1 = ex2_approx(e1);
                p2 = ex2_approx(e2);
            }
            acc[i] += p1;
            acc[j] += p2;
        }
    }

    // log_softmax of x = -tau*acc: x_i - xmax = -tau*(acc_i - amin)
    float t0 = fminf(acc[0], acc[1]),  t1 = fminf(acc[2], acc[3]);
    float t2 = fminf(acc[4], acc[5]),  t3 = fminf(acc[6], acc[7]);
    float t4 = fminf(acc[8], acc[9]),  t5 = fminf(acc[10], acc[11]);
    float t6 = fminf(acc[12], acc[13]), t7 = fminf(acc[14], acc[15]);
    t0 = fminf(t0, t1); t2 = fminf(t2, t3); t4 = fminf(t4, t5); t6 = fminf(t6, t7);
    float amin = fminf(fminf(t0, t2), fminf(t4, t6));

    const float nts = -TAU * LOG2E;
    float ex[MODES];
    float s = 0.0f;
#pragma unroll
    for (int i = 0; i < MODES; i++) {
        float e2v = ex2_approx((acc[i] - amin) * nts);
        ex[i] = e2v;
        s += e2v;
    }
    float lns = __log2f(s) * LN2;
    float inv_s = rcp_approx(s);

    float* alpha_out = out + (size_t)r * MODES;
    float* logit_out = out + (size_t)N * MODES + (size_t)r * MODES;
#pragma unroll
    for (int q = 0; q < 4; q++) {
        float4 a4, l4;
        float* ap = &a4.x;
        float* lp = &l4.x;
#pragma unroll
        for (int k = 0; k < 4; k++) {
            int i = 4 * q + k;
            ap[k] = ex[i] * inv_s;
            lp[k] = fmaf(-TAU, acc[i] - amin, -lns);
        }
        ((float4*)alpha_out)[q] = a4;
        ((float4*)logit_out)[q] = l4;
    }
}

extern "C" void kernel_launch(void* const* d_in, const int* in_sizes, int n_in,
                              void* d_out, int out_size) {
    const float* V      = (const float*)d_in[0];
    const float* w      = (const float*)d_in[1];
    const float* b      = (const float*)d_in[2];
    const float* gammas = (const float*)d_in[3];
    float* out = (float*)d_out;
    int N = in_sizes[0] / MODES;

    comp_vmin_kernel<<<VMIN_BLOCKS, 256>>>(V, N);
    int blocks = (N + 127) / 128;
    comp_main_kernel<<<blocks, 128>>>(V, w, b, gammas, out, N);
}